// round 14
// baseline (speedup 1.0000x reference)
#include <cuda_runtime.h>
#include <cuda_bf16.h>

// Problem constants (fixed by the dataset)
#define NN 50000
#define EE 850000
#define DIN 128
#define D1 64
#define H1 8
#define D2 16
#define NBMAX 256

// ---------------- scratch (__device__ globals) ---------------------------------
__device__ float    g_z1[NN * D1];
__device__ float    g_as1[NN * H1];
__device__ float    g_ad1[NN * H1];
__device__ unsigned g_ms1[H1];
__device__ unsigned g_md1[H1];
__device__ int      g_counts[NN];
__device__ int      g_rowptr[NN + 1];
__device__ int      g_rank[EE];       // edge rank within its dst (from hist)
__device__ int      g_csr[EE];
__device__ int      g_bsum[NBMAX];
__device__ float    g_h[NN * D1];
__device__ float    g_z2[NN * D2];
__device__ float    g_as2[NN];
__device__ float    g_ad2[NN];
__device__ unsigned g_ms2;
__device__ unsigned g_md2;

__device__ __forceinline__ unsigned fenc(float f) {
    unsigned u = __float_as_uint(f);
    return (u & 0x80000000u) ? ~u : (u | 0x80000000u);
}
__device__ __forceinline__ float fdec(unsigned u) {
    return __uint_as_float((u & 0x80000000u) ? (u & 0x7fffffffu) : ~u);
}
__device__ __forceinline__ float leaky(float e) { return e > 0.f ? e : 0.2f * e; }
__device__ __forceinline__ float dot4(float4 a, float4 b) {
    return a.x * b.x + a.y * b.y + a.z * b.z + a.w * b.w;
}

// ---------------- init: zero counts + max slots (R4 structure) ------------------
__global__ void init_kernel(int N) {
    int i = blockIdx.x * blockDim.x + threadIdx.x;
    if (i < N) g_counts[i] = 0;
    if (i < H1) { g_ms1[i] = 0u; g_md1[i] = 0u; }
    if (i == 0) { g_ms2 = 0u; g_md2 = 0u; }
}

// ---------------- GEMM1: 256-node tile, 4 nodes/thread, k-chunked smem ---------
// (R4's exact gemm1 — the measured-best variant.)
__global__ __launch_bounds__(256, 2)
void gemm1_kernel(const float* __restrict__ x,
                  const float* __restrict__ W1,
                  const float* __restrict__ a_src1,
                  const float* __restrict__ a_dst1,
                  int N) {
    __shared__ float sX[256 * 33];
    __shared__ float sW[32 * 64];
    __shared__ unsigned sMax[16];
    int t = threadIdx.x;
    if (t < 16) sMax[t] = 0u;
    int base = blockIdx.x << 8;
    int nl = t >> 2;
    int q  = t & 3;

    float4 acc[4][4];
#pragma unroll
    for (int i = 0; i < 4; i++)
#pragma unroll
        for (int j = 0; j < 4; j++) acc[i][j] = make_float4(0.f, 0.f, 0.f, 0.f);

    for (int kc = 0; kc < 4; kc++) {
        __syncthreads();
#pragma unroll
        for (int i = 0; i < 2; i++)
            ((float4*)sW)[t + (i << 8)] =
                __ldg((const float4*)(W1 + (kc << 11)) + t + (i << 8));
#pragma unroll
        for (int i = 0; i < 8; i++) {
            int idx = t + (i << 8);
            int node = idx >> 3, k4 = idx & 7;
            int n = base + node;
            float4 v = make_float4(0.f, 0.f, 0.f, 0.f);
            if (n < N) v = __ldg((const float4*)x + ((size_t)n << 5) + (kc << 3) + k4);
            float* dp = &sX[node * 33 + (k4 << 2)];
            dp[0] = v.x; dp[1] = v.y; dp[2] = v.z; dp[3] = v.w;
        }
        __syncthreads();
#pragma unroll 8
        for (int k = 0; k < 32; k++) {
            const float4* wr = (const float4*)&sW[(k << 6) + (q << 4)];
            float4 w0 = wr[0], w1 = wr[1], w2 = wr[2], w3 = wr[3];
#pragma unroll
            for (int i = 0; i < 4; i++) {
                float xv = sX[(nl + (i << 6)) * 33 + k];
                acc[i][0].x += xv * w0.x; acc[i][0].y += xv * w0.y;
                acc[i][0].z += xv * w0.z; acc[i][0].w += xv * w0.w;
                acc[i][1].x += xv * w1.x; acc[i][1].y += xv * w1.y;
                acc[i][1].z += xv * w1.z; acc[i][1].w += xv * w1.w;
                acc[i][2].x += xv * w2.x; acc[i][2].y += xv * w2.y;
                acc[i][2].z += xv * w2.z; acc[i][2].w += xv * w2.w;
                acc[i][3].x += xv * w3.x; acc[i][3].y += xv * w3.y;
                acc[i][3].z += xv * w3.z; acc[i][3].w += xv * w3.w;
            }
        }
    }

    int h0 = q << 1;
    const float4* As4 = (const float4*)a_src1;
    const float4* Ad4 = (const float4*)a_dst1;
    float4 s0 = __ldg(&As4[h0 * 2]),     s1 = __ldg(&As4[h0 * 2 + 1]);
    float4 s2 = __ldg(&As4[h0 * 2 + 2]), s3 = __ldg(&As4[h0 * 2 + 3]);
    float4 d0 = __ldg(&Ad4[h0 * 2]),     d1 = __ldg(&Ad4[h0 * 2 + 1]);
    float4 d2 = __ldg(&Ad4[h0 * 2 + 2]), d3 = __ldg(&Ad4[h0 * 2 + 3]);
#pragma unroll
    for (int i = 0; i < 4; i++) {
        int n = base + nl + (i << 6);
        if (n < N) {
            float4* zr = (float4*)&g_z1[((size_t)n << 6) + (q << 4)];
            zr[0] = acc[i][0]; zr[1] = acc[i][1];
            zr[2] = acc[i][2]; zr[3] = acc[i][3];
            float as0  = dot4(acc[i][0], s0) + dot4(acc[i][1], s1);
            float as1v = dot4(acc[i][2], s2) + dot4(acc[i][3], s3);
            float ad0  = dot4(acc[i][0], d0) + dot4(acc[i][1], d1);
            float ad1v = dot4(acc[i][2], d2) + dot4(acc[i][3], d3);
            g_as1[n * H1 + h0]     = as0;
            g_as1[n * H1 + h0 + 1] = as1v;
            g_ad1[n * H1 + h0]     = ad0;
            g_ad1[n * H1 + h0 + 1] = ad1v;
            atomicMax(&sMax[h0],         fenc(as0));
            atomicMax(&sMax[h0 + 1],     fenc(as1v));
            atomicMax(&sMax[8 + h0],     fenc(ad0));
            atomicMax(&sMax[8 + h0 + 1], fenc(ad1v));
        }
    }
    __syncthreads();
    if (t < 8)        atomicMax(&g_ms1[t], sMax[t]);
    else if (t < 16)  atomicMax(&g_md1[t - 8], sMax[t]);
}

// ---------------- CSR build (rank trick) ----------------------------------------
// hist: count + record each edge's rank within its destination (4 edges/thread).
__global__ void hist_kernel(const int* __restrict__ dst, int E) {
    int i = blockIdx.x * blockDim.x + threadIdx.x;
    int i4 = i << 2;
    if (i4 + 3 < E) {
        int4 d = __ldg((const int4*)dst + i);
        int r0 = atomicAdd(&g_counts[d.x], 1);
        int r1 = atomicAdd(&g_counts[d.y], 1);
        int r2 = atomicAdd(&g_counts[d.z], 1);
        int r3 = atomicAdd(&g_counts[d.w], 1);
        *(int4*)&g_rank[i4] = make_int4(r0, r1, r2, r3);
    } else {
        for (int j = i4; j < E && j < i4 + 4; j++)
            g_rank[j] = atomicAdd(&g_counts[dst[j]], 1);
    }
}

// Phase A: per-block sums of counts (256 elems / block)
__global__ void scanA_kernel(int N) {
    __shared__ int s[256];
    int t = threadIdx.x;
    int i = blockIdx.x * 256 + t;
    s[t] = (i < N) ? g_counts[i] : 0;
    __syncthreads();
#pragma unroll
    for (int off = 128; off > 0; off >>= 1) {
        if (t < off) s[t] += s[t + off];
        __syncthreads();
    }
    if (t == 0) g_bsum[blockIdx.x] = s[0];
}

// Phase C (merged lookback): warp 0 sums prior block sums; local scan -> rowptr.
__global__ void scanC_kernel(int N) {
    __shared__ int s[256];
    __shared__ int sbase;
    int t = threadIdx.x;
    int bid = blockIdx.x;
    if (t < 32) {
        int sum = 0;
        for (int j = t; j < bid; j += 32) sum += g_bsum[j];
#pragma unroll
        for (int off = 16; off > 0; off >>= 1)
            sum += __shfl_xor_sync(0xffffffffu, sum, off);
        if (t == 0) sbase = sum;
    }
    int i = bid * 256 + t;
    int v = (i < N) ? g_counts[i] : 0;
    s[t] = v;
    __syncthreads();
#pragma unroll
    for (int off = 1; off < 256; off <<= 1) {
        int u = (t >= off) ? s[t - off] : 0;
        __syncthreads();
        s[t] += u;
        __syncthreads();
    }
    int incl = s[t];
    int base = sbase;
    if (i < N) {
        g_rowptr[i] = base + incl - v;
        if (i == N - 1) g_rowptr[N] = base + incl;
    }
}

// scatter: atomic-free. slot = rowptr[dst] + rank[e]. 4 edges/thread.
__global__ void scatter_kernel(const int* __restrict__ src,
                               const int* __restrict__ dst, int E) {
    int i = blockIdx.x * blockDim.x + threadIdx.x;
    int i4 = i << 2;
    if (i4 + 3 < E) {
        int4 sv = __ldg((const int4*)src + i);
        int4 dv = __ldg((const int4*)dst + i);
        int4 rv = *(const int4*)&g_rank[i4];
        int p0 = __ldg(&g_rowptr[dv.x]) + rv.x;
        int p1 = __ldg(&g_rowptr[dv.y]) + rv.y;
        int p2 = __ldg(&g_rowptr[dv.z]) + rv.z;
        int p3 = __ldg(&g_rowptr[dv.w]) + rv.w;
        g_csr[p0] = sv.x;
        g_csr[p1] = sv.y;
        g_csr[p2] = sv.z;
        g_csr[p3] = sv.w;
    } else {
        for (int j = i4; j < E && j < i4 + 4; j++)
            g_csr[__ldg(&g_rowptr[dst[j]]) + g_rank[j]] = src[j];
    }
}

// ---------------- layer-1 aggregation: warp/node, 8 edges per iteration --------
__global__ void agg1_kernel(const float* __restrict__ b1, int N) {
    int w = (blockIdx.x * blockDim.x + threadIdx.x) >> 5;
    int lane = threadIdx.x & 31;
    if (w >= N) return;
    int n = w;
    int h8 = lane & 7;
    int grp = lane >> 3;
    int half = lane >> 4;
    int c = lane & 15;
    int hq = c >> 1;

    float ad_rep = g_ad1[n * H1 + h8];
    float M_rep  = fdec(g_ms1[h8]) + fdec(g_md1[h8]);

    float4 acc = make_float4(0.f, 0.f, 0.f, 0.f);
    float den = 0.f;
    int beg = g_rowptr[n], end = g_rowptr[n + 1];

    for (int i = beg; i < end; i += 8) {
        int ea = i + grp, eb = i + 4 + grp;
        bool va = ea < end, vb = eb < end;
        int s_a = va ? __ldg(&g_csr[ea]) : 0;
        int s_b = vb ? __ldg(&g_csr[eb]) : 0;
        float a_a = va ? __ldg(&g_as1[s_a * H1 + h8]) : 0.f;
        float a_b = vb ? __ldg(&g_as1[s_b * H1 + h8]) : 0.f;

        int se0 = __shfl_sync(0xffffffffu, s_a, half << 3);
        int se1 = __shfl_sync(0xffffffffu, s_a, (2 + half) << 3);
        int se2 = __shfl_sync(0xffffffffu, s_b, half << 3);
        int se3 = __shfl_sync(0xffffffffu, s_b, (2 + half) << 3);
        bool v0 = (i + half) < end;
        bool v1 = (i + 2 + half) < end;
        bool v2 = (i + 4 + half) < end;
        bool v3 = (i + 6 + half) < end;
        float4 z0 = v0 ? __ldg((const float4*)&g_z1[((size_t)se0 << 6) + (c << 2)]) : make_float4(0.f,0.f,0.f,0.f);
        float4 z1 = v1 ? __ldg((const float4*)&g_z1[((size_t)se1 << 6) + (c << 2)]) : make_float4(0.f,0.f,0.f,0.f);
        float4 z2 = v2 ? __ldg((const float4*)&g_z1[((size_t)se2 << 6) + (c << 2)]) : make_float4(0.f,0.f,0.f,0.f);
        float4 z3 = v3 ? __ldg((const float4*)&g_z1[((size_t)se3 << 6) + (c << 2)]) : make_float4(0.f,0.f,0.f,0.f);

        float w_a = va ? __expf(leaky(a_a + ad_rep) - M_rep) : 0.f;
        float w_b = vb ? __expf(leaky(a_b + ad_rep) - M_rep) : 0.f;
        den += w_a + w_b;

        float we0 = __shfl_sync(0xffffffffu, w_a, (half << 3) | hq);
        float we1 = __shfl_sync(0xffffffffu, w_a, ((2 + half) << 3) | hq);
        float we2 = __shfl_sync(0xffffffffu, w_b, (half << 3) | hq);
        float we3 = __shfl_sync(0xffffffffu, w_b, ((2 + half) << 3) | hq);

        acc.x += we0 * z0.x + we1 * z1.x + we2 * z2.x + we3 * z3.x;
        acc.y += we0 * z0.y + we1 * z1.y + we2 * z2.y + we3 * z3.y;
        acc.z += we0 * z0.z + we1 * z1.z + we2 * z2.z + we3 * z3.z;
        acc.w += we0 * z0.w + we1 * z1.w + we2 * z2.w + we3 * z3.w;
    }
    acc.x += __shfl_xor_sync(0xffffffffu, acc.x, 16);
    acc.y += __shfl_xor_sync(0xffffffffu, acc.y, 16);
    acc.z += __shfl_xor_sync(0xffffffffu, acc.z, 16);
    acc.w += __shfl_xor_sync(0xffffffffu, acc.w, 16);
    den += __shfl_xor_sync(0xffffffffu, den, 8);
    den += __shfl_xor_sync(0xffffffffu, den, 16);
    float dl = __shfl_sync(0xffffffffu, den, hq);

    if (lane < 16) {
        float4 bb = __ldg((const float4*)&b1[c << 2]);
        float inv = 1.f / (dl + 1e-16f);
        float o0 = acc.x * inv + bb.x;
        float o1 = acc.y * inv + bb.y;
        float o2 = acc.z * inv + bb.z;
        float o3 = acc.w * inv + bb.w;
        o0 = o0 > 0.f ? o0 : (__expf(o0) - 1.f);
        o1 = o1 > 0.f ? o1 : (__expf(o1) - 1.f);
        o2 = o2 > 0.f ? o2 : (__expf(o2) - 1.f);
        o3 = o3 > 0.f ? o3 : (__expf(o3) - 1.f);
        *(float4*)&g_h[((size_t)n << 6) + (c << 2)] = make_float4(o0, o1, o2, o3);
    }
}

// ---------------- layer-2 node transform (smem-staged) --------------------------
__global__ void node2_kernel(const float* __restrict__ W2,
                             const float* __restrict__ a_src2,
                             const float* __restrict__ a_dst2,
                             int N) {
    __shared__ float sH[16 * 64];
    __shared__ float sW2[64 * 16];
    __shared__ unsigned smS, smD;
    int t = threadIdx.x;
    if (t == 0) { smS = 0u; smD = 0u; }
    int base = blockIdx.x << 4;
    {
        int node = t >> 4, k4 = t & 15;
        int nn = base + node;
        float4 v = make_float4(0.f, 0.f, 0.f, 0.f);
        if (nn < N) v = __ldg((const float4*)&g_h[((size_t)nn << 6) + (k4 << 2)]);
        *(float4*)&sH[(node << 6) + (k4 << 2)] = v;
        ((float4*)sW2)[t] = __ldg((const float4*)W2 + t);
    }
    __syncthreads();

    int nl = t >> 4, c = t & 15;
    int n = base + nl;
    float acc = 0.f;
#pragma unroll 16
    for (int k = 0; k < 64; k++)
        acc += sH[(nl << 6) + k] * sW2[(k << 4) + c];

    float ts = acc * __ldg(&a_src2[c]);
    float td = acc * __ldg(&a_dst2[c]);
#pragma unroll
    for (int off = 8; off > 0; off >>= 1) {
        ts += __shfl_xor_sync(0xffffffffu, ts, off, 16);
        td += __shfl_xor_sync(0xffffffffu, td, off, 16);
    }
    if (n < N) {
        g_z2[n * D2 + c] = acc;
        if (c == 0) {
            g_as2[n] = ts;
            g_ad2[n] = td;
            atomicMax(&smS, fenc(ts));
            atomicMax(&smD, fenc(td));
        }
    }
    __syncthreads();
    if (t == 0) {
        atomicMax(&g_ms2, smS);
        atomicMax(&g_md2, smD);
    }
}

// ---------------- layer-2 aggregation: warp/node, 16 edges per iteration --------
__global__ void agg2_kernel(const float* __restrict__ b2,
                            float* __restrict__ out, int N) {
    int w = (blockIdx.x * blockDim.x + threadIdx.x) >> 5;
    int lane = threadIdx.x & 31;
    if (w >= N) return;
    int n = w;
    int el = lane & 15;
    int g8 = lane >> 2;
    int cq = lane & 3;

    float M2  = fdec(g_ms2) + fdec(g_md2);
    float adl = g_ad2[n];
    float4 acc = make_float4(0.f, 0.f, 0.f, 0.f);
    float den = 0.f;
    int beg = g_rowptr[n], end = g_rowptr[n + 1];

    for (int i = beg; i < end; i += 16) {
        int e = i + el;
        bool v = e < end;
        int s_l = v ? __ldg(&g_csr[e]) : 0;
        float a = v ? __ldg(&g_as2[s_l]) : 0.f;

        int se0 = __shfl_sync(0xffffffffu, s_l, g8);
        int se1 = __shfl_sync(0xffffffffu, s_l, 8 + g8);
        bool v0 = (i + g8) < end;
        bool v1 = (i + 8 + g8) < end;
        float4 z0 = v0 ? __ldg((const float4*)&g_z2[(size_t)se0 * D2 + (cq << 2)]) : make_float4(0.f,0.f,0.f,0.f);
        float4 z1 = v1 ? __ldg((const float4*)&g_z2[(size_t)se1 * D2 + (cq << 2)]) : make_float4(0.f,0.f,0.f,0.f);

        float wv = v ? __expf(leaky(a + adl) - M2) : 0.f;
        if (lane < 16) den += wv;

        float we0 = __shfl_sync(0xffffffffu, wv, g8);
        float we1 = __shfl_sync(0xffffffffu, wv, 8 + g8);
        acc.x += we0 * z0.x + we1 * z1.x;
        acc.y += we0 * z0.y + we1 * z1.y;
        acc.z += we0 * z0.z + we1 * z1.z;
        acc.w += we0 * z0.w + we1 * z1.w;
    }
#pragma unroll
    for (int off = 4; off < 32; off <<= 1) {
        acc.x += __shfl_xor_sync(0xffffffffu, acc.x, off);
        acc.y += __shfl_xor_sync(0xffffffffu, acc.y, off);
        acc.z += __shfl_xor_sync(0xffffffffu, acc.z, off);
        acc.w += __shfl_xor_sync(0xffffffffu, acc.w, off);
    }
    den += __shfl_xor_sync(0xffffffffu, den, 1);
    den += __shfl_xor_sync(0xffffffffu, den, 2);
    den += __shfl_xor_sync(0xffffffffu, den, 4);
    den += __shfl_xor_sync(0xffffffffu, den, 8);
    den = __shfl_sync(0xffffffffu, den, 0);

    if (lane < 4) {
        float4 bb = __ldg((const float4*)&b2[cq << 2]);
        float inv = 1.f / (den + 1e-16f);
        float4 o = make_float4(acc.x * inv + bb.x, acc.y * inv + bb.y,
                               acc.z * inv + bb.z, acc.w * inv + bb.w);
        *(float4*)&out[(size_t)n * D2 + (cq << 2)] = o;
    }
}

// ---------------- launch: R4 structure (init -> fork; side CSR || gemm1) --------
static inline int cdiv(int a, int b) { return (a + b - 1) / b; }

extern "C" void kernel_launch(void* const* d_in, const int* in_sizes, int n_in,
                              void* d_out, int out_size) {
    const float* x   = (const float*)d_in[0];
    const int*   ei  = (const int*)d_in[1];
    const float* W1  = (const float*)d_in[2];
    const float* as1 = (const float*)d_in[3];
    const float* ad1 = (const float*)d_in[4];
    const float* b1  = (const float*)d_in[5];
    const float* W2  = (const float*)d_in[6];
    const float* as2 = (const float*)d_in[7];
    const float* ad2 = (const float*)d_in[8];
    const float* b2  = (const float*)d_in[9];
    float* out = (float*)d_out;

    int N = in_sizes[0] / DIN;
    int E = in_sizes[1] / 2;
    const int* src = ei;
    const int* dst = ei + E;
    int NB = cdiv(N, 256);
    int E4 = cdiv(E, 4);

    static cudaStream_t s_side = nullptr;
    static cudaEvent_t ev_fork = nullptr, ev_join = nullptr;
    if (!s_side) {
        cudaStreamCreateWithFlags(&s_side, cudaStreamNonBlocking);
        cudaEventCreateWithFlags(&ev_fork, cudaEventDisableTiming);
        cudaEventCreateWithFlags(&ev_join, cudaEventDisableTiming);
    }

    // init (counts + max slots), then fork — R4's proven structure
    init_kernel<<<cdiv(N, 256), 256>>>(N);
    cudaEventRecord(ev_fork, 0);
    cudaStreamWaitEvent(s_side, ev_fork, 0);

    // side branch: CSR build (rank trick; merged scan; atomic-free scatter)
    hist_kernel<<<cdiv(E4, 256), 256, 0, s_side>>>(dst, E);
    scanA_kernel<<<NB, 256, 0, s_side>>>(N);
    scanC_kernel<<<NB, 256, 0, s_side>>>(N);
    scatter_kernel<<<cdiv(E4, 256), 256, 0, s_side>>>(src, dst, E);
    cudaEventRecord(ev_join, s_side);

    // main branch: feature transform (R4's 256-node tiles)
    gemm1_kernel<<<cdiv(N, 256), 256>>>(x, W1, as1, ad1, N);

    // join, then aggregation chain
    cudaStreamWaitEvent(0, ev_join, 0);
    agg1_kernel<<<cdiv(N * 32, 256), 256>>>(b1, N);
    node2_kernel<<<cdiv(N, 16), 256>>>(W2, as2, ad2, N);
    agg2_kernel<<<cdiv(N * 32, 256), 256>>>(b2, out, N);
}

// round 15
// speedup vs baseline: 1.0475x; 1.0475x over previous
#include <cuda_runtime.h>
#include <cuda_bf16.h>

// Problem constants (fixed by the dataset)
#define NN 50000
#define EE 850000
#define DIN 128
#define D1 64
#define H1 8
#define D2 16
#define NBMAX 256

// ---------------- scratch (__device__ globals) ---------------------------------
__device__ float    g_z1[NN * D1];
__device__ float    g_as1[NN * H1];
__device__ float    g_ad1[NN * H1];
__device__ unsigned g_ms1[H1];
__device__ unsigned g_md1[H1];
__device__ int      g_counts[NN];
__device__ int      g_rowptr[NN + 1];
__device__ int      g_rank[EE];       // edge rank within its dst (from hist)
__device__ int      g_csr[EE];
__device__ int      g_bsum[NBMAX];
__device__ float    g_h[NN * D1];
__device__ float    g_z2[NN * D2];
__device__ float    g_as2[NN];
__device__ float    g_ad2[NN];
__device__ unsigned g_ms2;
__device__ unsigned g_md2;

__device__ __forceinline__ unsigned fenc(float f) {
    unsigned u = __float_as_uint(f);
    return (u & 0x80000000u) ? ~u : (u | 0x80000000u);
}
__device__ __forceinline__ float fdec(unsigned u) {
    return __uint_as_float((u & 0x80000000u) ? (u & 0x7fffffffu) : ~u);
}
__device__ __forceinline__ float leaky(float e) { return e > 0.f ? e : 0.2f * e; }
__device__ __forceinline__ float dot4(float4 a, float4 b) {
    return a.x * b.x + a.y * b.y + a.z * b.z + a.w * b.w;
}

// ---------------- init: zero counts + max slots ---------------------------------
__global__ void init_kernel(int N) {
    int i = blockIdx.x * blockDim.x + threadIdx.x;
    if (i < N) g_counts[i] = 0;
    if (i < H1) { g_ms1[i] = 0u; g_md1[i] = 0u; }
    if (i == 0) { g_ms2 = 0u; g_md2 = 0u; }
}

// ---------------- GEMM1: 128-node tile, 128 threads, 4 nodes/thread ------------
// (R12's measured-better gemm1 — fine-grained blocks, no residency imbalance.)
__global__ __launch_bounds__(128, 4)
void gemm1_kernel(const float* __restrict__ x,
                  const float* __restrict__ W1,
                  const float* __restrict__ a_src1,
                  const float* __restrict__ a_dst1,
                  int N) {
    __shared__ float sX[128 * 33];
    __shared__ float sW[32 * 64];
    __shared__ unsigned sMax[16];
    int t = threadIdx.x;
    if (t < 16) sMax[t] = 0u;
    int base = blockIdx.x << 7;
    int nl = t >> 2;
    int q  = t & 3;

    float4 acc[4][4];
#pragma unroll
    for (int i = 0; i < 4; i++)
#pragma unroll
        for (int j = 0; j < 4; j++) acc[i][j] = make_float4(0.f, 0.f, 0.f, 0.f);

    for (int kc = 0; kc < 4; kc++) {
        __syncthreads();
#pragma unroll
        for (int i = 0; i < 4; i++)
            ((float4*)sW)[t + (i << 7)] =
                __ldg((const float4*)(W1 + (kc << 11)) + t + (i << 7));
#pragma unroll
        for (int i = 0; i < 8; i++) {
            int idx = t + (i << 7);
            int node = idx >> 3, k4 = idx & 7;
            int n = base + node;
            float4 v = make_float4(0.f, 0.f, 0.f, 0.f);
            if (n < N) v = __ldg((const float4*)x + ((size_t)n << 5) + (kc << 3) + k4);
            float* dp = &sX[node * 33 + (k4 << 2)];
            dp[0] = v.x; dp[1] = v.y; dp[2] = v.z; dp[3] = v.w;
        }
        __syncthreads();
#pragma unroll 8
        for (int k = 0; k < 32; k++) {
            const float4* wr = (const float4*)&sW[(k << 6) + (q << 4)];
            float4 w0 = wr[0], w1 = wr[1], w2 = wr[2], w3 = wr[3];
#pragma unroll
            for (int i = 0; i < 4; i++) {
                float xv = sX[(nl + (i << 5)) * 33 + k];
                acc[i][0].x += xv * w0.x; acc[i][0].y += xv * w0.y;
                acc[i][0].z += xv * w0.z; acc[i][0].w += xv * w0.w;
                acc[i][1].x += xv * w1.x; acc[i][1].y += xv * w1.y;
                acc[i][1].z += xv * w1.z; acc[i][1].w += xv * w1.w;
                acc[i][2].x += xv * w2.x; acc[i][2].y += xv * w2.y;
                acc[i][2].z += xv * w2.z; acc[i][2].w += xv * w2.w;
                acc[i][3].x += xv * w3.x; acc[i][3].y += xv * w3.y;
                acc[i][3].z += xv * w3.z; acc[i][3].w += xv * w3.w;
            }
        }
    }

    int h0 = q << 1;
    const float4* As4 = (const float4*)a_src1;
    const float4* Ad4 = (const float4*)a_dst1;
    float4 s0 = __ldg(&As4[h0 * 2]),     s1 = __ldg(&As4[h0 * 2 + 1]);
    float4 s2 = __ldg(&As4[h0 * 2 + 2]), s3 = __ldg(&As4[h0 * 2 + 3]);
    float4 d0 = __ldg(&Ad4[h0 * 2]),     d1 = __ldg(&Ad4[h0 * 2 + 1]);
    float4 d2 = __ldg(&Ad4[h0 * 2 + 2]), d3 = __ldg(&Ad4[h0 * 2 + 3]);
#pragma unroll
    for (int i = 0; i < 4; i++) {
        int n = base + nl + (i << 5);
        if (n < N) {
            float4* zr = (float4*)&g_z1[((size_t)n << 6) + (q << 4)];
            zr[0] = acc[i][0]; zr[1] = acc[i][1];
            zr[2] = acc[i][2]; zr[3] = acc[i][3];
            float as0  = dot4(acc[i][0], s0) + dot4(acc[i][1], s1);
            float as1v = dot4(acc[i][2], s2) + dot4(acc[i][3], s3);
            float ad0  = dot4(acc[i][0], d0) + dot4(acc[i][1], d1);
            float ad1v = dot4(acc[i][2], d2) + dot4(acc[i][3], d3);
            g_as1[n * H1 + h0]     = as0;
            g_as1[n * H1 + h0 + 1] = as1v;
            g_ad1[n * H1 + h0]     = ad0;
            g_ad1[n * H1 + h0 + 1] = ad1v;
            atomicMax(&sMax[h0],         fenc(as0));
            atomicMax(&sMax[h0 + 1],     fenc(as1v));
            atomicMax(&sMax[8 + h0],     fenc(ad0));
            atomicMax(&sMax[8 + h0 + 1], fenc(ad1v));
        }
    }
    __syncthreads();
    if (t < 8)        atomicMax(&g_ms1[t], sMax[t]);
    else if (t < 16)  atomicMax(&g_md1[t - 8], sMax[t]);
}

// ---------------- CSR build (rank trick) ----------------------------------------
__global__ void hist_kernel(const int* __restrict__ dst, int E) {
    int i = blockIdx.x * blockDim.x + threadIdx.x;
    int i4 = i << 2;
    if (i4 + 3 < E) {
        int4 d = __ldg((const int4*)dst + i);
        int r0 = atomicAdd(&g_counts[d.x], 1);
        int r1 = atomicAdd(&g_counts[d.y], 1);
        int r2 = atomicAdd(&g_counts[d.z], 1);
        int r3 = atomicAdd(&g_counts[d.w], 1);
        *(int4*)&g_rank[i4] = make_int4(r0, r1, r2, r3);
    } else {
        for (int j = i4; j < E && j < i4 + 4; j++)
            g_rank[j] = atomicAdd(&g_counts[dst[j]], 1);
    }
}

// Phase A: per-block sums of counts (256 elems / block)
__global__ void scanA_kernel(int N) {
    __shared__ int s[256];
    int t = threadIdx.x;
    int i = blockIdx.x * 256 + t;
    s[t] = (i < N) ? g_counts[i] : 0;
    __syncthreads();
#pragma unroll
    for (int off = 128; off > 0; off >>= 1) {
        if (t < off) s[t] += s[t + off];
        __syncthreads();
    }
    if (t == 0) g_bsum[blockIdx.x] = s[0];
}

// Phase C: bsum-only lookback + shuffle block scan (2 barriers, no ladder).
__global__ void scanC_kernel(int N) {
    __shared__ int wsum[8];
    __shared__ int sbase;
    int t = threadIdx.x;
    int bid = blockIdx.x;
    int lane = t & 31;
    int wid = t >> 5;

    if (wid == 0) {
        int sum = 0;
        for (int j = lane; j < bid; j += 32) sum += g_bsum[j];
#pragma unroll
        for (int off = 16; off > 0; off >>= 1)
            sum += __shfl_xor_sync(0xffffffffu, sum, off);
        if (lane == 0) sbase = sum;
    }

    int i = bid * 256 + t;
    int v = (i < N) ? g_counts[i] : 0;
    int sc = v;
#pragma unroll
    for (int off = 1; off < 32; off <<= 1) {
        int u = __shfl_up_sync(0xffffffffu, sc, off);
        if (lane >= off) sc += u;
    }
    if (lane == 31) wsum[wid] = sc;
    __syncthreads();
    if (wid == 0 && lane < 8) {
        int ws = wsum[lane];
        int s = ws;
#pragma unroll
        for (int off = 1; off < 8; off <<= 1) {
            int u = __shfl_up_sync(0xffu, s, off);
            if (lane >= off) s += u;
        }
        wsum[lane] = s - ws;            // exclusive warp offsets
    }
    __syncthreads();
    int incl = sc + wsum[wid];
    int base = sbase;
    if (i < N) {
        g_rowptr[i] = base + incl - v;
        if (i == N - 1) g_rowptr[N] = base + incl;
    }
}

// scatter: atomic-free, 8 edges/thread (deep MLP on the dst->rowptr gather).
__global__ void scatter_kernel(const int* __restrict__ src,
                               const int* __restrict__ dst, int E) {
    int i = blockIdx.x * blockDim.x + threadIdx.x;
    int i8 = i << 3;
    if (i8 + 7 < E) {
        int4 sva = __ldg((const int4*)src + (i << 1));
        int4 svb = __ldg((const int4*)src + (i << 1) + 1);
        int4 dva = __ldg((const int4*)dst + (i << 1));
        int4 dvb = __ldg((const int4*)dst + (i << 1) + 1);
        int4 rva = *(const int4*)&g_rank[i8];
        int4 rvb = *(const int4*)&g_rank[i8 + 4];
        int p0 = __ldg(&g_rowptr[dva.x]) + rva.x;
        int p1 = __ldg(&g_rowptr[dva.y]) + rva.y;
        int p2 = __ldg(&g_rowptr[dva.z]) + rva.z;
        int p3 = __ldg(&g_rowptr[dva.w]) + rva.w;
        int p4 = __ldg(&g_rowptr[dvb.x]) + rvb.x;
        int p5 = __ldg(&g_rowptr[dvb.y]) + rvb.y;
        int p6 = __ldg(&g_rowptr[dvb.z]) + rvb.z;
        int p7 = __ldg(&g_rowptr[dvb.w]) + rvb.w;
        g_csr[p0] = sva.x; g_csr[p1] = sva.y;
        g_csr[p2] = sva.z; g_csr[p3] = sva.w;
        g_csr[p4] = svb.x; g_csr[p5] = svb.y;
        g_csr[p6] = svb.z; g_csr[p7] = svb.w;
    } else {
        for (int j = i8; j < E && j < i8 + 8; j++)
            g_csr[__ldg(&g_rowptr[dst[j]]) + g_rank[j]] = src[j];
    }
}

// ---------------- layer-1 aggregation: warp/node, 8 edges per iteration --------
__global__ void agg1_kernel(const float* __restrict__ b1, int N) {
    int w = (blockIdx.x * blockDim.x + threadIdx.x) >> 5;
    int lane = threadIdx.x & 31;
    if (w >= N) return;
    int n = w;
    int h8 = lane & 7;
    int grp = lane >> 3;
    int half = lane >> 4;
    int c = lane & 15;
    int hq = c >> 1;

    float ad_rep = g_ad1[n * H1 + h8];
    float M_rep  = fdec(g_ms1[h8]) + fdec(g_md1[h8]);

    float4 acc = make_float4(0.f, 0.f, 0.f, 0.f);
    float den = 0.f;
    int beg = g_rowptr[n], end = g_rowptr[n + 1];

    for (int i = beg; i < end; i += 8) {
        int ea = i + grp, eb = i + 4 + grp;
        bool va = ea < end, vb = eb < end;
        int s_a = va ? __ldg(&g_csr[ea]) : 0;
        int s_b = vb ? __ldg(&g_csr[eb]) : 0;
        float a_a = va ? __ldg(&g_as1[s_a * H1 + h8]) : 0.f;
        float a_b = vb ? __ldg(&g_as1[s_b * H1 + h8]) : 0.f;

        int se0 = __shfl_sync(0xffffffffu, s_a, half << 3);
        int se1 = __shfl_sync(0xffffffffu, s_a, (2 + half) << 3);
        int se2 = __shfl_sync(0xffffffffu, s_b, half << 3);
        int se3 = __shfl_sync(0xffffffffu, s_b, (2 + half) << 3);
        bool v0 = (i + half) < end;
        bool v1 = (i + 2 + half) < end;
        bool v2 = (i + 4 + half) < end;
        bool v3 = (i + 6 + half) < end;
        float4 z0 = v0 ? __ldg((const float4*)&g_z1[((size_t)se0 << 6) + (c << 2)]) : make_float4(0.f,0.f,0.f,0.f);
        float4 z1 = v1 ? __ldg((const float4*)&g_z1[((size_t)se1 << 6) + (c << 2)]) : make_float4(0.f,0.f,0.f,0.f);
        float4 z2 = v2 ? __ldg((const float4*)&g_z1[((size_t)se2 << 6) + (c << 2)]) : make_float4(0.f,0.f,0.f,0.f);
        float4 z3 = v3 ? __ldg((const float4*)&g_z1[((size_t)se3 << 6) + (c << 2)]) : make_float4(0.f,0.f,0.f,0.f);

        float w_a = va ? __expf(leaky(a_a + ad_rep) - M_rep) : 0.f;
        float w_b = vb ? __expf(leaky(a_b + ad_rep) - M_rep) : 0.f;
        den += w_a + w_b;

        float we0 = __shfl_sync(0xffffffffu, w_a, (half << 3) | hq);
        float we1 = __shfl_sync(0xffffffffu, w_a, ((2 + half) << 3) | hq);
        float we2 = __shfl_sync(0xffffffffu, w_b, (half << 3) | hq);
        float we3 = __shfl_sync(0xffffffffu, w_b, ((2 + half) << 3) | hq);

        acc.x += we0 * z0.x + we1 * z1.x + we2 * z2.x + we3 * z3.x;
        acc.y += we0 * z0.y + we1 * z1.y + we2 * z2.y + we3 * z3.y;
        acc.z += we0 * z0.z + we1 * z1.z + we2 * z2.z + we3 * z3.z;
        acc.w += we0 * z0.w + we1 * z1.w + we2 * z2.w + we3 * z3.w;
    }
    acc.x += __shfl_xor_sync(0xffffffffu, acc.x, 16);
    acc.y += __shfl_xor_sync(0xffffffffu, acc.y, 16);
    acc.z += __shfl_xor_sync(0xffffffffu, acc.z, 16);
    acc.w += __shfl_xor_sync(0xffffffffu, acc.w, 16);
    den += __shfl_xor_sync(0xffffffffu, den, 8);
    den += __shfl_xor_sync(0xffffffffu, den, 16);
    float dl = __shfl_sync(0xffffffffu, den, hq);

    if (lane < 16) {
        float4 bb = __ldg((const float4*)&b1[c << 2]);
        float inv = 1.f / (dl + 1e-16f);
        float o0 = acc.x * inv + bb.x;
        float o1 = acc.y * inv + bb.y;
        float o2 = acc.z * inv + bb.z;
        float o3 = acc.w * inv + bb.w;
        o0 = o0 > 0.f ? o0 : (__expf(o0) - 1.f);
        o1 = o1 > 0.f ? o1 : (__expf(o1) - 1.f);
        o2 = o2 > 0.f ? o2 : (__expf(o2) - 1.f);
        o3 = o3 > 0.f ? o3 : (__expf(o3) - 1.f);
        *(float4*)&g_h[((size_t)n << 6) + (c << 2)] = make_float4(o0, o1, o2, o3);
    }
}

// ---------------- layer-2 node transform (smem-staged) --------------------------
__global__ void node2_kernel(const float* __restrict__ W2,
                             const float* __restrict__ a_src2,
                             const float* __restrict__ a_dst2,
                             int N) {
    __shared__ float sH[16 * 64];
    __shared__ float sW2[64 * 16];
    __shared__ unsigned smS, smD;
    int t = threadIdx.x;
    if (t == 0) { smS = 0u; smD = 0u; }
    int base = blockIdx.x << 4;
    {
        int node = t >> 4, k4 = t & 15;
        int nn = base + node;
        float4 v = make_float4(0.f, 0.f, 0.f, 0.f);
        if (nn < N) v = __ldg((const float4*)&g_h[((size_t)nn << 6) + (k4 << 2)]);
        *(float4*)&sH[(node << 6) + (k4 << 2)] = v;
        ((float4*)sW2)[t] = __ldg((const float4*)W2 + t);
    }
    __syncthreads();

    int nl = t >> 4, c = t & 15;
    int n = base + nl;
    float acc = 0.f;
#pragma unroll 16
    for (int k = 0; k < 64; k++)
        acc += sH[(nl << 6) + k] * sW2[(k << 4) + c];

    float ts = acc * __ldg(&a_src2[c]);
    float td = acc * __ldg(&a_dst2[c]);
#pragma unroll
    for (int off = 8; off > 0; off >>= 1) {
        ts += __shfl_xor_sync(0xffffffffu, ts, off, 16);
        td += __shfl_xor_sync(0xffffffffu, td, off, 16);
    }
    if (n < N) {
        g_z2[n * D2 + c] = acc;
        if (c == 0) {
            g_as2[n] = ts;
            g_ad2[n] = td;
            atomicMax(&smS, fenc(ts));
            atomicMax(&smD, fenc(td));
        }
    }
    __syncthreads();
    if (t == 0) {
        atomicMax(&g_ms2, smS);
        atomicMax(&g_md2, smD);
    }
}

// ---------------- layer-2 aggregation: warp/node, 16 edges per iteration --------
__global__ void agg2_kernel(const float* __restrict__ b2,
                            float* __restrict__ out, int N) {
    int w = (blockIdx.x * blockDim.x + threadIdx.x) >> 5;
    int lane = threadIdx.x & 31;
    if (w >= N) return;
    int n = w;
    int el = lane & 15;
    int g8 = lane >> 2;
    int cq = lane & 3;

    float M2  = fdec(g_ms2) + fdec(g_md2);
    float adl = g_ad2[n];
    float4 acc = make_float4(0.f, 0.f, 0.f, 0.f);
    float den = 0.f;
    int beg = g_rowptr[n], end = g_rowptr[n + 1];

    for (int i = beg; i < end; i += 16) {
        int e = i + el;
        bool v = e < end;
        int s_l = v ? __ldg(&g_csr[e]) : 0;
        float a = v ? __ldg(&g_as2[s_l]) : 0.f;

        int se0 = __shfl_sync(0xffffffffu, s_l, g8);
        int se1 = __shfl_sync(0xffffffffu, s_l, 8 + g8);
        bool v0 = (i + g8) < end;
        bool v1 = (i + 8 + g8) < end;
        float4 z0 = v0 ? __ldg((const float4*)&g_z2[(size_t)se0 * D2 + (cq << 2)]) : make_float4(0.f,0.f,0.f,0.f);
        float4 z1 = v1 ? __ldg((const float4*)&g_z2[(size_t)se1 * D2 + (cq << 2)]) : make_float4(0.f,0.f,0.f,0.f);

        float wv = v ? __expf(leaky(a + adl) - M2) : 0.f;
        if (lane < 16) den += wv;

        float we0 = __shfl_sync(0xffffffffu, wv, g8);
        float we1 = __shfl_sync(0xffffffffu, wv, 8 + g8);
        acc.x += we0 * z0.x + we1 * z1.x;
        acc.y += we0 * z0.y + we1 * z1.y;
        acc.z += we0 * z0.z + we1 * z1.z;
        acc.w += we0 * z0.w + we1 * z1.w;
    }
#pragma unroll
    for (int off = 4; off < 32; off <<= 1) {
        acc.x += __shfl_xor_sync(0xffffffffu, acc.x, off);
        acc.y += __shfl_xor_sync(0xffffffffu, acc.y, off);
        acc.z += __shfl_xor_sync(0xffffffffu, acc.z, off);
        acc.w += __shfl_xor_sync(0xffffffffu, acc.w, off);
    }
    den += __shfl_xor_sync(0xffffffffu, den, 1);
    den += __shfl_xor_sync(0xffffffffu, den, 2);
    den += __shfl_xor_sync(0xffffffffu, den, 4);
    den += __shfl_xor_sync(0xffffffffu, den, 8);
    den = __shfl_sync(0xffffffffu, den, 0);

    if (lane < 4) {
        float4 bb = __ldg((const float4*)&b2[cq << 2]);
        float inv = 1.f / (den + 1e-16f);
        float4 o = make_float4(acc.x * inv + bb.x, acc.y * inv + bb.y,
                               acc.z * inv + bb.z, acc.w * inv + bb.w);
        *(float4*)&out[(size_t)n * D2 + (cq << 2)] = o;
    }
}

// ---------------- launch: init -> fork; side CSR || gemm1; join; agg chain ------
static inline int cdiv(int a, int b) { return (a + b - 1) / b; }

extern "C" void kernel_launch(void* const* d_in, const int* in_sizes, int n_in,
                              void* d_out, int out_size) {
    const float* x   = (const float*)d_in[0];
    const int*   ei  = (const int*)d_in[1];
    const float* W1  = (const float*)d_in[2];
    const float* as1 = (const float*)d_in[3];
    const float* ad1 = (const float*)d_in[4];
    const float* b1  = (const float*)d_in[5];
    const float* W2  = (const float*)d_in[6];
    const float* as2 = (const float*)d_in[7];
    const float* ad2 = (const float*)d_in[8];
    const float* b2  = (const float*)d_in[9];
    float* out = (float*)d_out;

    int N = in_sizes[0] / DIN;
    int E = in_sizes[1] / 2;
    const int* src = ei;
    const int* dst = ei + E;
    int NB = cdiv(N, 256);
    int E4 = cdiv(E, 4);
    int E8 = cdiv(E, 8);

    static cudaStream_t s_side = nullptr;
    static cudaEvent_t ev_fork = nullptr, ev_join = nullptr;
    if (!s_side) {
        cudaStreamCreateWithFlags(&s_side, cudaStreamNonBlocking);
        cudaEventCreateWithFlags(&ev_fork, cudaEventDisableTiming);
        cudaEventCreateWithFlags(&ev_join, cudaEventDisableTiming);
    }

    // init (counts + max slots), then fork
    init_kernel<<<cdiv(N, 256), 256>>>(N);
    cudaEventRecord(ev_fork, 0);
    cudaStreamWaitEvent(s_side, ev_fork, 0);

    // side branch: CSR build (rank trick; shuffle scanC; deep-MLP scatter)
    hist_kernel<<<cdiv(E4, 256), 256, 0, s_side>>>(dst, E);
    scanA_kernel<<<NB, 256, 0, s_side>>>(N);
    scanC_kernel<<<NB, 256, 0, s_side>>>(N);
    scatter_kernel<<<cdiv(E8, 256), 256, 0, s_side>>>(src, dst, E);
    cudaEventRecord(ev_join, s_side);

    // main branch: feature transform (fine-grained 128-node tiles)
    gemm1_kernel<<<cdiv(N, 128), 128>>>(x, W1, as1, ad1, N);

    // join, then aggregation chain
    cudaStreamWaitEvent(0, ev_join, 0);
    agg1_kernel<<<cdiv(N * 32, 256), 256>>>(b1, N);
    node2_kernel<<<cdiv(N, 16), 256>>>(W2, as2, ad2, N);
    agg2_kernel<<<cdiv(N * 32, 256), 256>>>(b2, out, N);
}